// round 6
// baseline (speedup 1.0000x reference)
#include <cuda_runtime.h>
#include <cuda_bf16.h>
#include <cstdint>

// f_z[b,i] = z[b,i] + sum_{j<i} h[b, i*(i-1)/2 + j] * z[b,j]
// h packed strictly-lower-triangular row-major. HBM-streaming bound.
//
// Warp handles row pair (i, 511-i) (balanced). h read as aligned-DOWN
// LDG.128 quads; z is register-resident across the warp (zq[r] = z quad of
// lane+32r). Element k of h-quad v pairs with z[4v+k-mis]: own register for
// k>=mis, one shfl_up for k<mis. Head/tail junk elements are zeroed in the
// h registers. No per-element LDS, no scalar edge loads.

#define DIM 512
#define HLEN ((DIM * (DIM - 1)) / 2)   // 130816
#define THREADS 256
#define FULL 0xffffffffu

template<int MIS, int NSTEPS>
__device__ __forceinline__ float row_sum(const float* __restrict__ hb, unsigned off,
                                         const float4* __restrict__ zq,
                                         int len, int lane)
{
    const float4* h4 = (const float4*)(hb + (off & ~3u));
    const int e_end = len + MIS;            // elements [MIS, e_end) are valid
    const int nq = (e_end + 3) >> 2;

    // front-batched independent predicated loads
    float4 hv[NSTEPS];
    #pragma unroll
    for (int st = 0; st < NSTEPS; ++st) {
        int v = lane + 32 * st;
        hv[st] = make_float4(0.f, 0.f, 0.f, 0.f);
        if (v < nq) hv[st] = __ldcs(h4 + v);
    }
    // head junk: lane0 quad0, comps k < MIS
    if (MIS >= 1 && lane == 0) {
        hv[0].x = 0.f;
        if (MIS >= 2) hv[0].y = 0.f;
        if (MIS >= 3) hv[0].z = 0.f;
    }
    // tail junk: boundary quad v_b = e_end>>2, comps k >= (e_end&3)
    {
        const int c = e_end & 3;
        if (c) {
            const int v_b = e_end >> 2;
            #pragma unroll
            for (int st = 0; st < NSTEPS; ++st) {
                if (st == (v_b >> 5) && lane == (v_b & 31)) {
                    if (c <= 1) hv[st].y = 0.f;
                    if (c <= 2) hv[st].z = 0.f;
                    hv[st].w = 0.f;
                }
            }
        }
    }

    float s0 = 0.f, s1 = 0.f, s2 = 0.f, s3 = 0.f;
    #pragma unroll
    for (int st = 0; st < NSTEPS; ++st) {
        const float4 own  = (st < 4) ? zq[st] : zq[0];      // st==4 own is junk-only
        if (MIS == 0) {
            s0 = fmaf(hv[st].x, own.x, s0);
            s1 = fmaf(hv[st].y, own.y, s1);
            s2 = fmaf(hv[st].z, own.z, s2);
            s3 = fmaf(hv[st].w, own.w, s3);
        } else {
            const float4 psrc = (st >= 1) ? zq[st - 1] : zq[0];  // lane31 supply for lane0
            if (MIS == 1) {
                float pw = __shfl_sync(FULL, (lane == 31) ? psrc.w : own.w, (lane + 31) & 31);
                s0 = fmaf(hv[st].x, pw,    s0);
                s1 = fmaf(hv[st].y, own.x, s1);
                s2 = fmaf(hv[st].z, own.y, s2);
                s3 = fmaf(hv[st].w, own.z, s3);
            } else if (MIS == 2) {
                float pz = __shfl_sync(FULL, (lane == 31) ? psrc.z : own.z, (lane + 31) & 31);
                float pw = __shfl_sync(FULL, (lane == 31) ? psrc.w : own.w, (lane + 31) & 31);
                s0 = fmaf(hv[st].x, pz,    s0);
                s1 = fmaf(hv[st].y, pw,    s1);
                s2 = fmaf(hv[st].z, own.x, s2);
                s3 = fmaf(hv[st].w, own.y, s3);
            } else { // MIS == 3
                float py = __shfl_sync(FULL, (lane == 31) ? psrc.y : own.y, (lane + 31) & 31);
                float pz = __shfl_sync(FULL, (lane == 31) ? psrc.z : own.z, (lane + 31) & 31);
                float pw = __shfl_sync(FULL, (lane == 31) ? psrc.w : own.w, (lane + 31) & 31);
                s0 = fmaf(hv[st].x, py,    s0);
                s1 = fmaf(hv[st].y, pz,    s1);
                s2 = fmaf(hv[st].z, pw,    s2);
                s3 = fmaf(hv[st].w, own.x, s3);
            }
        }
    }
    return (s0 + s1) + (s2 + s3);
}

template<int NSTEPS>
__device__ __forceinline__ float row_dispatch(const float* __restrict__ hb, unsigned off,
                                              const float4* __restrict__ zq,
                                              int len, int lane)
{
    switch (off & 3u) {
        case 0:  return row_sum<0, NSTEPS>(hb, off, zq, len, lane);
        case 1:  return row_sum<1, NSTEPS>(hb, off, zq, len, lane);
        case 2:  return row_sum<2, NSTEPS>(hb, off, zq, len, lane);
        default: return row_sum<3, NSTEPS>(hb, off, zq, len, lane);
    }
}

__global__ __launch_bounds__(THREADS) void LinearMap_kernel(
    const float* __restrict__ z,
    const float* __restrict__ h,
    float* __restrict__ out,
    int out_size)
{
    __shared__ float zs[DIM];

    const int b    = blockIdx.x >> 5;          // / 32
    const int pg   = blockIdx.x & 31;
    const int tid  = threadIdx.x;
    const int warp = tid >> 5;
    const int lane = tid & 31;

    // stage z[b] (vectorized), then distribute into registers per warp
    const float4* zb4 = (const float4*)(z + (size_t)b * DIM);
    if (tid < DIM / 4) ((float4*)zs)[tid] = zb4[tid];
    __syncthreads();

    float4 zq[4];
    #pragma unroll
    for (int r = 0; r < 4; ++r)
        zq[r] = ((const float4*)zs)[lane + 32 * r];   // conflict-free LDS.128

    const int ia = pg * 8 + warp;              // 0..255
    const int ib = DIM - 1 - ia;               // 256..511
    const unsigned offa = (unsigned)(ia * (ia - 1) / 2);
    const unsigned offb = (unsigned)(ib * (ib - 1) / 2);
    const float* hb = h + (size_t)b * HLEN;

    float suma = row_dispatch<3>(hb, offa, zq, ia, lane);  // nq_a <= 65
    float sumb = row_dispatch<5>(hb, offb, zq, ib, lane);  // nq_b <= 129

    #pragma unroll
    for (int o = 16; o; o >>= 1) {
        suma += __shfl_xor_sync(FULL, suma, o);
        sumb += __shfl_xor_sync(FULL, sumb, o);
    }

    if (lane == 0) {
        float* ob = out + (size_t)b * DIM;
        ob[ia] = zs[ia] + suma;
        ob[ib] = zs[ib] + sumb;
    }

    // logdet / tail zeroing (d_out is poisoned)
    if (blockIdx.x == 0) {
        const int nfz = (int)(gridDim.x >> 5) * DIM;
        for (int k = nfz + tid; k < out_size; k += THREADS) out[k] = 0.0f;
    }
}

extern "C" void kernel_launch(void* const* d_in, const int* in_sizes, int n_in,
                              void* d_out, int out_size)
{
    const float* z = (const float*)d_in[0];   // [batch, 512]
    const float* h = (const float*)d_in[1];   // [batch, 130816]
    float* out = (float*)d_out;

    const int batch = in_sizes[0] / DIM;      // 256

    dim3 grid(batch * 32);                    // 8192 identical CTAs
    LinearMap_kernel<<<grid, THREADS>>>(z, h, out, out_size);
}